// round 1
// baseline (speedup 1.0000x reference)
#include <cuda_runtime.h>

#define BB 8
#define HH 48
#define WW 48
#define LL (HH*WW)      /* 2304 */
#define DM 96
#define DI 192
#define NS 16
#define RR 6
#define KK 4
#define CH 32           /* scan steps staged per chunk */

/* ---------------- scratch (static device globals; no allocation) ---------------- */
__device__ float g_qpre [BB*LL*DI];
__device__ float g_kvpre[BB*LL*DI];
__device__ float g_qc   [BB*LL*DI];
__device__ float g_kvc  [BB*LL*DI];
__device__ float g_z    [BB*LL*DI];
__device__ float g_dt   [BB*KK*LL*DI];
__device__ float g_Bs   [BB*KK*LL*NS];
__device__ float g_Cs   [BB*KK*LL*NS];
__device__ float g_ydir [BB*KK*LL*DI];
__device__ float g_w1T  [DM*2*DI];     /* [m][o] 96x384 */
__device__ float g_w2T  [DM*DI];       /* [m][o] 96x192 */
__device__ float g_xpwT [KK*DI*38];    /* [k][d][c]     */
__device__ float g_dtwT [KK*RR*DI];    /* [k][r][d]     */
__device__ float g_woutT[DI*DM];       /* [e][m] 192x96 */

/* ---------------- weight transposes (coalesced access layouts) ---------------- */
__global__ void k_prep(const float* __restrict__ w1, const float* __restrict__ w2,
                       const float* __restrict__ xpw, const float* __restrict__ dtw,
                       const float* __restrict__ wout) {
    const int O1 = 384*96;            /* w1 */
    const int O2 = O1 + 192*96;       /* w2 */
    const int O3 = O2 + KK*38*192;    /* xpw */
    const int O4 = O3 + KK*192*6;     /* dtw */
    const int O5 = O4 + 96*192;       /* wout */
    int i = blockIdx.x*blockDim.x + threadIdx.x;
    if (i < O1) {
        int o = i / 96, m = i % 96;
        g_w1T[m*384 + o] = w1[i];
    } else if (i < O2) {
        int j = i - O1; int o = j/96, m = j%96;
        g_w2T[m*192 + o] = w2[j];
    } else if (i < O3) {
        int a = i - O2; int k = a/7296; int rem = a%7296; int c = rem/192, d = rem%192;
        g_xpwT[k*(DI*38) + d*38 + c] = xpw[a];
    } else if (i < O4) {
        int e = i - O3; int k = e/1152; int rem = e%1152; int d = rem/6, r = rem%6;
        g_dtwT[(k*RR + r)*DI + d] = dtw[e];
    } else if (i < O5) {
        int f = i - O4; int m = f/192, d = f%192;
        g_woutT[d*DM + m] = wout[f];
    }
}

/* ---------------- input projection: out = x @ W^T ---------------- */
/* which=0: q path (384 rows -> g_qpre rows [0,192), g_z rows [192,384))
   which=1: kv path (192 rows -> g_kvpre). block = 96 threads, 4 outputs/thread */
__global__ void k_inproj(const float* __restrict__ x, int which) {
    int bp = blockIdx.x;
    int tid = threadIdx.x;              /* 96 */
    __shared__ float xv[DM];
    xv[tid] = x[bp*DM + tid];
    __syncthreads();
    int nrows = which ? DI : 2*DI;
    if (tid*4 >= nrows) return;
    const float* wT = which ? g_w2T : g_w1T;
    int o0 = tid*4;
    float4 acc = make_float4(0.f,0.f,0.f,0.f);
    #pragma unroll 8
    for (int m = 0; m < DM; m++) {
        float xm = xv[m];
        float4 wv = *(const float4*)(wT + m*nrows + o0);
        acc.x = fmaf(xm, wv.x, acc.x);
        acc.y = fmaf(xm, wv.y, acc.y);
        acc.z = fmaf(xm, wv.z, acc.z);
        acc.w = fmaf(xm, wv.w, acc.w);
    }
    float* outp;
    if (which)          outp = g_kvpre + bp*DI + o0;
    else if (o0 < DI)   outp = g_qpre  + bp*DI + o0;
    else                outp = g_z     + bp*DI + (o0 - DI);
    *(float4*)outp = acc;
}

/* ---------------- depthwise 3x3 conv (SAME, zero pad) + bias + SiLU ---------------- */
__global__ void k_conv(const float* __restrict__ cw, const float* __restrict__ cb, int which) {
    int idx = blockIdx.x*blockDim.x + threadIdx.x;
    if (idx >= BB*LL*DI) return;
    const float* in = which ? g_kvpre : g_qpre;
    float*       out = which ? g_kvc  : g_qc;
    int d = idx % DI; int bp = idx / DI; int p = bp % LL; int b = bp / LL;
    int h = p / WW, w = p % WW;
    float acc = cb[d];
    #pragma unroll
    for (int i = 0; i < 3; i++) {
        int hh = h + i - 1;
        if (hh < 0 || hh >= HH) continue;
        #pragma unroll
        for (int j = 0; j < 3; j++) {
            int ww = w + j - 1;
            if (ww < 0 || ww >= WW) continue;
            acc = fmaf(in[(b*LL + hh*WW + ww)*DI + d], cw[d*9 + i*3 + j], acc);
        }
    }
    out[idx] = acc / (1.f + __expf(-acc));   /* silu */
}

/* ---------------- x_proj + dt projection + softplus, scattered to scan order ----------------
   block = 192 threads, one block per (b,p). Stores dt (b,k,l,d), Bs/Cs (b,k,l,n). */
__global__ void k_xproj(const float* __restrict__ dtb) {
    int bp = blockIdx.x; int p = bp % LL; int b = bp / LL;
    int tid = threadIdx.x;              /* 192 */
    __shared__ float kv[DI];
    __shared__ float cbuf[KK][38];
    kv[tid] = g_kvc[bp*DI + tid];
    __syncthreads();
    if (tid < KK*38) {
        int k = tid / 38, c = tid % 38;
        const float* wp = g_xpwT + k*(DI*38) + c;
        float a0=0.f, a1=0.f, a2=0.f, a3=0.f;
        #pragma unroll 4
        for (int dd = 0; dd < DI; dd += 4) {
            a0 = fmaf(kv[dd+0], wp[(dd+0)*38], a0);
            a1 = fmaf(kv[dd+1], wp[(dd+1)*38], a1);
            a2 = fmaf(kv[dd+2], wp[(dd+2)*38], a2);
            a3 = fmaf(kv[dd+3], wp[(dd+3)*38], a3);
        }
        cbuf[k][c] = (a0+a1) + (a2+a3);
    }
    __syncthreads();
    int Tp = (p % WW)*HH + p / WW;      /* transpose map, self-inverse for H==W */
    int lks[KK] = { p, Tp, LL-1-p, LL-1-Tp };
    if (tid < 128) {                    /* B/C scatter: 4k * 32 values */
        int k = tid >> 5, j = tid & 31;
        int base = ((b*KK + k)*LL + lks[k]) * NS;
        float v = cbuf[k][6 + j];
        if (j < 16) g_Bs[base + j]        = v;
        else        g_Cs[base + (j-16)]   = v;
    }
    #pragma unroll
    for (int k = 0; k < KK; k++) {
        float acc = dtb[k*DI + tid];
        #pragma unroll
        for (int r = 0; r < RR; r++)
            acc = fmaf(cbuf[k][r], g_dtwT[(k*RR + r)*DI + tid], acc);
        float sp = (acc > 20.f) ? acc : log1pf(__expf(acc));   /* softplus */
        g_dt[((b*KK + k)*LL + lks[k])*DI + tid] = sp;
    }
}

/* ---------------- selective scan ----------------
   thread = (b,k,d,n); block = 256 threads = 16 d's x 16 n's, one (b,k).
   32-step smem staging of dt/x/B/C; 16-lane shuffle reduce for y. */
__global__ void __launch_bounds__(256) k_scan(const float* __restrict__ A_logs,
                                              const float* __restrict__ Ds) {
    int bk = blockIdx.y; int b = bk >> 2; int k = bk & 3;
    int d0 = blockIdx.x << 4;
    int tid = threadIdx.x;
    int dd = tid >> 4, n = tid & 15;
    int d = d0 + dd;
    float A  = -__expf(A_logs[(k*DI + d)*NS + n]);
    float Dv = Ds[k*DI + d];
    float h = 0.f;
    __shared__ float s_dt[CH*16], s_x[CH*16], s_B[CH*16], s_C[CH*16];
    __shared__ int   s_p[CH];
    const int baseL = bk * LL;
    const float* dtp = g_dt + baseL*DI;
    const float* Bp  = g_Bs + baseL*NS;
    const float* Cp  = g_Cs + baseL*NS;
    const float* xp  = g_qc + b*LL*DI;
    float*       yp  = g_ydir + baseL*DI;

    for (int l0 = 0; l0 < LL; l0 += CH) {
        #pragma unroll
        for (int i = tid; i < CH*16; i += 256) {
            int r = i >> 4, c = i & 15;
            int l = l0 + r;
            int pos;
            if      (k == 0) pos = l;
            else if (k == 1) pos = (l % WW)*HH + l / WW;
            else if (k == 2) pos = LL-1-l;
            else { int lf = LL-1-l; pos = (lf % WW)*HH + lf / WW; }
            if (c == 0) s_p[r] = pos;
            s_dt[i] = dtp[l*DI + d0 + c];
            s_B[i]  = Bp [l*NS + c];
            s_C[i]  = Cp [l*NS + c];
            s_x[i]  = xp [pos*DI + d0 + c];
        }
        __syncthreads();
        #pragma unroll 4
        for (int r = 0; r < CH; r++) {
            float dt = s_dt[(r<<4) + dd];
            float x  = s_x [(r<<4) + dd];
            float Bv = s_B [(r<<4) + n];
            float Cv = s_C [(r<<4) + n];
            float dA = __expf(dt * A);
            h = fmaf(h, dA, dt * x * Bv);
            float y = h * Cv;
            y += __shfl_xor_sync(0xffffffffu, y, 8);
            y += __shfl_xor_sync(0xffffffffu, y, 4);
            y += __shfl_xor_sync(0xffffffffu, y, 2);
            y += __shfl_xor_sync(0xffffffffu, y, 1);
            if (n == 0) yp[(l0 + r)*DI + d] = fmaf(Dv, x, y);
        }
        __syncthreads();
    }
}

/* ---------------- direction merge + LayerNorm + z + out_proj ---------------- */
__global__ void k_combine(const float* __restrict__ lnw, const float* __restrict__ lnb,
                          float* __restrict__ out) {
    int bp = blockIdx.x; int p = bp % LL; int b = bp / LL;
    int tid = threadIdx.x;              /* 192 */
    int Tp = (p % WW)*HH + p / WW;
    int b4 = b * KK;
    float v = g_ydir[((b4+0)*LL + p)*DI + tid]
            + g_ydir[((b4+2)*LL + (LL-1-p))*DI + tid]
            + g_ydir[((b4+1)*LL + Tp)*DI + tid]
            + g_ydir[((b4+3)*LL + (LL-1-Tp))*DI + tid];
    __shared__ float red[6];
    __shared__ float sarr[DI];
    float s = v;
    #pragma unroll
    for (int o = 16; o; o >>= 1) s += __shfl_xor_sync(0xffffffffu, s, o);
    if ((tid & 31) == 0) red[tid >> 5] = s;
    __syncthreads();
    float mu = (red[0]+red[1]+red[2]+red[3]+red[4]+red[5]) * (1.f/DI);
    __syncthreads();
    float dv = v - mu;
    float s2 = dv*dv;
    #pragma unroll
    for (int o = 16; o; o >>= 1) s2 += __shfl_xor_sync(0xffffffffu, s2, o);
    if ((tid & 31) == 0) red[tid >> 5] = s2;
    __syncthreads();
    float var = (red[0]+red[1]+red[2]+red[3]+red[4]+red[5]) * (1.f/DI);
    float rstd = rsqrtf(var + 1e-5f);
    sarr[tid] = fmaf(dv*rstd, lnw[tid], lnb[tid]) + g_z[bp*DI + tid];
    __syncthreads();
    if (tid < DM) {
        const float* wp = g_woutT + tid;   /* [e][m], lanes over m coalesced */
        float a0=0.f, a1=0.f, a2=0.f, a3=0.f;
        #pragma unroll 4
        for (int e = 0; e < DI; e += 4) {
            a0 = fmaf(sarr[e+0], wp[(e+0)*DM], a0);
            a1 = fmaf(sarr[e+1], wp[(e+1)*DM], a1);
            a2 = fmaf(sarr[e+2], wp[(e+2)*DM], a2);
            a3 = fmaf(sarr[e+3], wp[(e+3)*DM], a3);
        }
        out[(b*DM + tid)*LL + p] = (a0+a1) + (a2+a3);
    }
}

/* ---------------- launch ---------------- */
extern "C" void kernel_launch(void* const* d_in, const int* in_sizes, int n_in,
                              void* d_out, int out_size) {
    const float* q_x    = (const float*)d_in[0];
    const float* kv_x   = (const float*)d_in[1];
    const float* w1     = (const float*)d_in[2];
    const float* w2     = (const float*)d_in[3];
    const float* cw     = (const float*)d_in[4];
    const float* cb     = (const float*)d_in[5];
    const float* xpw    = (const float*)d_in[6];
    const float* dtw    = (const float*)d_in[7];
    const float* dtb    = (const float*)d_in[8];
    const float* A_logs = (const float*)d_in[9];
    const float* Ds     = (const float*)d_in[10];
    const float* lnw    = (const float*)d_in[11];
    const float* lnb    = (const float*)d_in[12];
    const float* wout   = (const float*)d_in[13];
    float* out = (float*)d_out;

    k_prep<<<(107520 + 255)/256, 256>>>(w1, w2, xpw, dtw, wout);
    k_inproj<<<BB*LL, 96>>>(q_x, 0);
    k_inproj<<<BB*LL, 96>>>(kv_x, 1);
    int ct = BB*LL*DI;
    k_conv<<<(ct + 255)/256, 256>>>(cw, cb, 0);
    k_conv<<<(ct + 255)/256, 256>>>(cw, cb, 1);
    k_xproj<<<BB*LL, 192>>>(dtb);
    dim3 sg(DI/16, BB*KK);
    k_scan<<<sg, 256>>>(A_logs, Ds);
    k_combine<<<BB*LL, 192>>>(lnw, lnb, out);
}

// round 2
// speedup vs baseline: 1.3856x; 1.3856x over previous
#include <cuda_runtime.h>

#define BB 8
#define HH 48
#define WW 48
#define LL (HH*WW)      /* 2304 */
#define DM 96
#define DI 192
#define NS 16
#define RR 6
#define KK 4
#define CH 32           /* scan steps staged per chunk */
#define BL (BB*LL)      /* 18432 */

#define GBM 128
#define GBN 32
#define GBK 32

/* ---------------- scratch (static device globals; no allocation) ---------------- */
__device__ float g_qpre [BL*DI];
__device__ float g_kvpre[BL*DI];
__device__ float g_qc   [BL*DI];
__device__ float g_kvc  [BL*DI];
__device__ float g_z    [BL*DI];
__device__ float g_xdbl [BL*152];
__device__ float g_dtr  [BB*KK*LL*RR];
__device__ float g_Bs   [BB*KK*LL*NS];
__device__ float g_Cs   [BB*KK*LL*NS];
__device__ float g_ydir [BB*KK*LL*DI];   /* position-space per direction */
__device__ float g_yln  [BL*DI];
__device__ float g_w1T  [DM*2*DI];       /* [m][o] 96x384 */
__device__ float g_w2T  [DM*DI];         /* [m][o] 96x192 */
__device__ float g_xpwT [DI*152];        /* [d][k*38+c]   */
__device__ float g_woutT[DI*DM];         /* [e][m] 192x96 */

/* ---------------- weight transposes ---------------- */
__global__ void k_prep(const float* __restrict__ w1, const float* __restrict__ w2,
                       const float* __restrict__ xpw, const float* __restrict__ wout) {
    const int O1 = 384*96;
    const int O2 = O1 + 192*96;
    const int O3 = O2 + KK*38*192;
    const int O4 = O3 + 96*192;
    int i = blockIdx.x*blockDim.x + threadIdx.x;
    if (i < O1) {
        int o = i / 96, m = i % 96;
        g_w1T[m*384 + o] = w1[i];
    } else if (i < O2) {
        int j = i - O1; int o = j/96, m = j%96;
        g_w2T[m*192 + o] = w2[j];
    } else if (i < O3) {
        int a = i - O2; int k = a/7296; int rem = a%7296; int c = rem/192, d = rem%192;
        g_xpwT[d*152 + k*38 + c] = xpw[a];
    } else if (i < O4) {
        int f = i - O3; int m = f/192, d = f%192;
        g_woutT[d*DM + m] = wout[f];
    }
}

/* ---------------- register-tiled GEMM:  C[M,N] = A[M,K] * Bt[K,N] ----------------
   mode 0: plain store to C0[M,N]
   mode 1: split cols: col<192 -> C0[m*192+col], else C1[m*192+col-192]
   mode 2: transposed store: C0[(b*96 + col)*LL + p], m = b*LL + p */
__global__ void __launch_bounds__(256) k_gemm(const float* __restrict__ A,
                                              const float* __restrict__ Bt,
                                              float* __restrict__ C0,
                                              float* __restrict__ C1,
                                              int K, int N, int mode) {
    __shared__ float As[GBM][36];
    __shared__ float Bs[GBK][GBN];
    __shared__ float Cs[GBN][GBM];
    int m0 = blockIdx.x * GBM;
    int n0 = blockIdx.y * GBN;
    int tid = threadIdx.x;
    int tm = tid >> 3, tn = tid & 7;
    float acc[4][4] = {};
    for (int k0 = 0; k0 < K; k0 += GBK) {
        #pragma unroll
        for (int i = 0; i < 4; i++) {
            int q = tid + 256*i;
            int m = q >> 3, f = (q & 7) << 2;
            float4 v = *(const float4*)(A + (size_t)(m0+m)*K + k0 + f);
            As[m][f+0]=v.x; As[m][f+1]=v.y; As[m][f+2]=v.z; As[m][f+3]=v.w;
        }
        #pragma unroll
        for (int i = 0; i < 4; i++) {
            int q = tid + 256*i;
            int kk = q >> 5, n = q & 31;
            float v = 0.f;
            if (n0+n < N) v = Bt[(size_t)(k0+kk)*N + n0+n];
            Bs[kk][n] = v;
        }
        __syncthreads();
        #pragma unroll
        for (int k = 0; k < GBK; k++) {
            float a0 = As[tm*4+0][k], a1 = As[tm*4+1][k];
            float a2 = As[tm*4+2][k], a3 = As[tm*4+3][k];
            float4 bv = *(const float4*)(&Bs[k][tn*4]);
            acc[0][0] = fmaf(a0, bv.x, acc[0][0]); acc[0][1] = fmaf(a0, bv.y, acc[0][1]);
            acc[0][2] = fmaf(a0, bv.z, acc[0][2]); acc[0][3] = fmaf(a0, bv.w, acc[0][3]);
            acc[1][0] = fmaf(a1, bv.x, acc[1][0]); acc[1][1] = fmaf(a1, bv.y, acc[1][1]);
            acc[1][2] = fmaf(a1, bv.z, acc[1][2]); acc[1][3] = fmaf(a1, bv.w, acc[1][3]);
            acc[2][0] = fmaf(a2, bv.x, acc[2][0]); acc[2][1] = fmaf(a2, bv.y, acc[2][1]);
            acc[2][2] = fmaf(a2, bv.z, acc[2][2]); acc[2][3] = fmaf(a2, bv.w, acc[2][3]);
            acc[3][0] = fmaf(a3, bv.x, acc[3][0]); acc[3][1] = fmaf(a3, bv.y, acc[3][1]);
            acc[3][2] = fmaf(a3, bv.z, acc[3][2]); acc[3][3] = fmaf(a3, bv.w, acc[3][3]);
        }
        __syncthreads();
    }
    if (mode == 0) {
        #pragma unroll
        for (int i = 0; i < 4; i++)
            #pragma unroll
            for (int j = 0; j < 4; j++) {
                int n = n0 + tn*4 + j;
                if (n < N) C0[(size_t)(m0 + tm*4 + i)*N + n] = acc[i][j];
            }
    } else if (mode == 1) {
        #pragma unroll
        for (int i = 0; i < 4; i++)
            #pragma unroll
            for (int j = 0; j < 4; j++) {
                int n = n0 + tn*4 + j;
                int m = m0 + tm*4 + i;
                if (n < 192) C0[(size_t)m*192 + n] = acc[i][j];
                else         C1[(size_t)m*192 + (n-192)] = acc[i][j];
            }
    } else {
        #pragma unroll
        for (int i = 0; i < 4; i++)
            #pragma unroll
            for (int j = 0; j < 4; j++)
                Cs[tn*4+j][tm*4+i] = acc[i][j];
        __syncthreads();
        int b = m0 / LL, p0 = m0 % LL;   /* GBM=128 divides LL=2304: no b-crossing */
        for (int e = tid; e < GBN*GBM; e += 256) {
            int n = e >> 7, p = e & 127;
            C0[(size_t)(b*DM + n0 + n)*LL + p0 + p] = Cs[n][p];
        }
    }
}

/* ---------------- depthwise 3x3 conv + bias + SiLU (both paths, one launch) ---------------- */
__global__ void k_conv(const float* __restrict__ cw, const float* __restrict__ cb) {
    int idx = blockIdx.x*blockDim.x + threadIdx.x;
    const int ct = BL*DI;
    if (idx >= 2*ct) return;
    int which = idx >= ct;
    int id = which ? idx - ct : idx;
    const float* in  = which ? g_kvpre : g_qpre;
    float*       out = which ? g_kvc   : g_qc;
    int d = id % DI; int bp = id / DI; int p = bp % LL; int b = bp / LL;
    int h = p / WW, w = p % WW;
    float acc = cb[d];
    #pragma unroll
    for (int i = 0; i < 3; i++) {
        int hh = h + i - 1;
        if (hh < 0 || hh >= HH) continue;
        #pragma unroll
        for (int j = 0; j < 3; j++) {
            int ww = w + j - 1;
            if (ww < 0 || ww >= WW) continue;
            acc = fmaf(in[(b*LL + hh*WW + ww)*DI + d], cw[d*9 + i*3 + j], acc);
        }
    }
    out[id] = acc / (1.f + __expf(-acc));   /* silu */
}

/* ---------------- scatter x_dbl -> dtr / B / C in per-direction scan order ---------------- */
__global__ void k_scatter() {
    int idx = blockIdx.x*blockDim.x + threadIdx.x;
    if (idx >= BL*152) return;
    int bp = idx / 152, t = idx % 152;
    int k = t / 38, c = t % 38;
    int p = bp % LL, b = bp / LL;
    int Tp = (p % WW)*HH + p / WW;
    int lk = (k==0) ? p : (k==1) ? Tp : (k==2) ? (LL-1-p) : (LL-1-Tp);
    float v = g_xdbl[idx];
    int base = (b*KK + k)*LL + lk;
    if (c < 6)       g_dtr[base*RR + c]       = v;
    else if (c < 22) g_Bs [base*NS + (c-6)]   = v;
    else             g_Cs [base*NS + (c-22)]  = v;
}

/* ---------------- selective scan ----------------
   thread = (b,k,d,n); block = 256 = 16 d x 16 n, one (b,k).
   dt computed in staging from rank-6 dtr (kills the 113MB dt stream).
   y written in OUTPUT-position space (gather map is self-consistent). */
__global__ void __launch_bounds__(256) k_scan(const float* __restrict__ A_logs,
                                              const float* __restrict__ Ds,
                                              const float* __restrict__ dtw,
                                              const float* __restrict__ dtb) {
    int bk = blockIdx.y; int b = bk >> 2; int k = bk & 3;
    int d0 = blockIdx.x << 4;
    int tid = threadIdx.x;
    int dd = tid >> 4, n = tid & 15;
    int d = d0 + dd;
    __shared__ float wdt[16][6], bdt[16];
    if (tid < 96) { int c = tid/6, r = tid%6; wdt[c][r] = dtw[(k*DI + d0 + c)*RR + r]; }
    if (tid < 16) bdt[tid] = dtb[k*DI + d0 + tid];
    float A  = -__expf(A_logs[(k*DI + d)*NS + n]);
    float Dv = Ds[k*DI + d];
    float h = 0.f;
    __shared__ float s_dt[CH*16], s_x[CH*16], s_B[CH*16], s_C[CH*16];
    __shared__ int   s_p[CH];
    const int baseL = bk * LL;
    const float* dtrp = g_dtr + baseL*RR;
    const float* Bp   = g_Bs  + baseL*NS;
    const float* Cp   = g_Cs  + baseL*NS;
    const float* xp   = g_qc  + b*LL*DI;
    float*       yp   = g_ydir + baseL*DI;
    __syncthreads();

    for (int l0 = 0; l0 < LL; l0 += CH) {
        #pragma unroll
        for (int i = tid; i < CH*16; i += 256) {
            int r = i >> 4, c = i & 15;
            int l = l0 + r;
            int pos;
            if      (k == 0) pos = l;
            else if (k == 1) pos = (l % WW)*HH + l / WW;
            else if (k == 2) pos = LL-1-l;
            else { int lf = LL-1-l; pos = (lf % WW)*HH + lf / WW; }
            if (c == 0) s_p[r] = pos;
            const float* dr = dtrp + l*RR;
            float a = bdt[c];
            #pragma unroll
            for (int rr = 0; rr < RR; rr++) a = fmaf(dr[rr], wdt[c][rr], a);
            s_dt[i] = (a > 20.f) ? a : __logf(1.f + __expf(a));   /* softplus */
            s_B[i]  = Bp[l*NS + c];
            s_C[i]  = Cp[l*NS + c];
            s_x[i]  = xp[pos*DI + d0 + c];
        }
        __syncthreads();
        #pragma unroll 4
        for (int r = 0; r < CH; r++) {
            float dt = s_dt[(r<<4) + dd];
            float x  = s_x [(r<<4) + dd];
            float Bv = s_B [(r<<4) + n];
            float Cv = s_C [(r<<4) + n];
            float dA = __expf(dt * A);
            h = fmaf(h, dA, dt * x * Bv);
            float y = h * Cv;
            y += __shfl_xor_sync(0xffffffffu, y, 8);
            y += __shfl_xor_sync(0xffffffffu, y, 4);
            y += __shfl_xor_sync(0xffffffffu, y, 2);
            y += __shfl_xor_sync(0xffffffffu, y, 1);
            if (n == 0) yp[s_p[r]*DI + d] = fmaf(Dv, x, y);
        }
        __syncthreads();
    }
}

/* ---------------- direction merge + LayerNorm + z ---------------- */
__global__ void k_lnz(const float* __restrict__ lnw, const float* __restrict__ lnb) {
    int bp = blockIdx.x; int p = bp % LL; int b = bp / LL;
    int tid = threadIdx.x;              /* 192 */
    int b4 = b * KK;
    float v = g_ydir[((b4+0)*LL + p)*DI + tid]
            + g_ydir[((b4+1)*LL + p)*DI + tid]
            + g_ydir[((b4+2)*LL + p)*DI + tid]
            + g_ydir[((b4+3)*LL + p)*DI + tid];
    __shared__ float red[6];
    float s = v;
    #pragma unroll
    for (int o = 16; o; o >>= 1) s += __shfl_xor_sync(0xffffffffu, s, o);
    if ((tid & 31) == 0) red[tid >> 5] = s;
    __syncthreads();
    float mu = (red[0]+red[1]+red[2]+red[3]+red[4]+red[5]) * (1.f/DI);
    __syncthreads();
    float dv = v - mu;
    float s2 = dv*dv;
    #pragma unroll
    for (int o = 16; o; o >>= 1) s2 += __shfl_xor_sync(0xffffffffu, s2, o);
    if ((tid & 31) == 0) red[tid >> 5] = s2;
    __syncthreads();
    float var = (red[0]+red[1]+red[2]+red[3]+red[4]+red[5]) * (1.f/DI);
    float rstd = rsqrtf(var + 1e-5f);
    g_yln[bp*DI + tid] = fmaf(dv*rstd, lnw[tid], lnb[tid]) + g_z[bp*DI + tid];
}

/* ---------------- launch ---------------- */
extern "C" void kernel_launch(void* const* d_in, const int* in_sizes, int n_in,
                              void* d_out, int out_size) {
    const float* q_x    = (const float*)d_in[0];
    const float* kv_x   = (const float*)d_in[1];
    const float* w1     = (const float*)d_in[2];
    const float* w2     = (const float*)d_in[3];
    const float* cw     = (const float*)d_in[4];
    const float* cb     = (const float*)d_in[5];
    const float* xpw    = (const float*)d_in[6];
    const float* dtw    = (const float*)d_in[7];
    const float* dtb    = (const float*)d_in[8];
    const float* A_logs = (const float*)d_in[9];
    const float* Ds     = (const float*)d_in[10];
    const float* lnw    = (const float*)d_in[11];
    const float* lnb    = (const float*)d_in[12];
    const float* wout   = (const float*)d_in[13];
    float* out = (float*)d_out;

    float *p_qpre, *p_kvpre, *p_kvc, *p_z, *p_xdbl, *p_yln;
    float *p_w1T, *p_w2T, *p_xpwT, *p_woutT;
    cudaGetSymbolAddress((void**)&p_qpre,  g_qpre);
    cudaGetSymbolAddress((void**)&p_kvpre, g_kvpre);
    cudaGetSymbolAddress((void**)&p_kvc,   g_kvc);
    cudaGetSymbolAddress((void**)&p_z,     g_z);
    cudaGetSymbolAddress((void**)&p_xdbl,  g_xdbl);
    cudaGetSymbolAddress((void**)&p_yln,   g_yln);
    cudaGetSymbolAddress((void**)&p_w1T,   g_w1T);
    cudaGetSymbolAddress((void**)&p_w2T,   g_w2T);
    cudaGetSymbolAddress((void**)&p_xpwT,  g_xpwT);
    cudaGetSymbolAddress((void**)&p_woutT, g_woutT);

    const int prepN = 384*96 + 192*96 + KK*38*192 + 96*192;
    k_prep<<<(prepN + 255)/256, 256>>>(w1, w2, xpw, wout);

    /* in_proj q (split q/z) and kv */
    k_gemm<<<dim3(BL/GBM, 384/GBN), 256>>>(q_x,  p_w1T, p_qpre, p_z, 96, 384, 1);
    k_gemm<<<dim3(BL/GBM, 192/GBN), 256>>>(kv_x, p_w2T, p_kvpre, nullptr, 96, 192, 0);

    k_conv<<<(2*BL*DI + 255)/256, 256>>>(cw, cb);

    /* x_proj: [BL,192] x [192,152] */
    k_gemm<<<dim3(BL/GBM, (152+GBN-1)/GBN), 256>>>(p_kvc, p_xpwT, p_xdbl, nullptr, 192, 152, 0);
    k_scatter<<<(BL*152 + 255)/256, 256>>>();

    dim3 sg(DI/16, BB*KK);
    k_scan<<<sg, 256>>>(A_logs, Ds, dtw, dtb);

    k_lnz<<<BL, 192>>>(lnw, lnb);

    /* out_proj with transposed store: [BL,192] x [192,96] -> (B,DM,H,W) */
    k_gemm<<<dim3(BL/GBM, 96/GBN), 256>>>(p_yln, p_woutT, out, nullptr, 192, 96, 2);
}

// round 3
// speedup vs baseline: 1.3868x; 1.0009x over previous
#include <cuda_runtime.h>

#define BB 8
#define HH 48
#define WW 48
#define LL (HH*WW)      /* 2304 */
#define DM 96
#define DI 192
#define NS 16
#define RR 6
#define KK 4
#define CH 32           /* scan steps staged per chunk */
#define BL (BB*LL)      /* 18432 */

#define GBM 128
#define GBN 32
#define GBK 32

/* ---------------- scratch (static device globals; no allocation) ---------------- */
__device__ float g_qpre [BL*DI];
__device__ float g_kvpre[BL*DI];
__device__ float g_qc   [BL*DI];
__device__ float g_kvc  [BL*DI];
__device__ float g_z    [BL*DI];
__device__ float g_xdbl [BL*152];
__device__ float g_dtr  [BB*KK*LL*RR];
__device__ float g_Bs   [BB*KK*LL*NS];
__device__ float g_Cs   [BB*KK*LL*NS];
__device__ float g_ydir [BB*KK*LL*DI];   /* position-space per direction */
__device__ float g_yln  [BL*DI];
__device__ float g_w1T  [DM*2*DI];       /* [m][o] 96x384 */
__device__ float g_w2T  [DM*DI];         /* [m][o] 96x192 */
__device__ float g_xpwT [DI*152];        /* [d][k*38+c]   */
__device__ float g_woutT[DI*DM];         /* [e][m] 192x96 */

/* ---------------- weight transposes ---------------- */
__global__ void k_prep(const float* __restrict__ w1, const float* __restrict__ w2,
                       const float* __restrict__ xpw, const float* __restrict__ wout) {
    const int O1 = 384*96;
    const int O2 = O1 + 192*96;
    const int O3 = O2 + KK*38*192;
    const int O4 = O3 + 96*192;
    int i = blockIdx.x*blockDim.x + threadIdx.x;
    if (i < O1) {
        int o = i / 96, m = i % 96;
        g_w1T[m*384 + o] = w1[i];
    } else if (i < O2) {
        int j = i - O1; int o = j/96, m = j%96;
        g_w2T[m*192 + o] = w2[j];
    } else if (i < O3) {
        int a = i - O2; int k = a/7296; int rem = a%7296; int c = rem/192, d = rem%192;
        g_xpwT[d*152 + k*38 + c] = xpw[a];
    } else if (i < O4) {
        int f = i - O3; int m = f/192, d = f%192;
        g_woutT[d*DM + m] = wout[f];
    }
}

/* ---------------- register-tiled GEMM:  C[M,N] = A[M,K] * Bt[K,N] ----------------
   mode 0: plain store to C0[M,N]
   mode 1: split cols: col<192 -> C0[m*192+col], else C1[m*192+col-192]
   mode 2: transposed store: C0[(b*96 + col)*LL + p], m = b*LL + p */
__global__ void __launch_bounds__(256) k_gemm(const float* __restrict__ A,
                                              const float* __restrict__ Bt,
                                              float* __restrict__ C0,
                                              float* __restrict__ C1,
                                              int K, int N, int mode) {
    __shared__ float As[GBM][36];
    __shared__ float Bs[GBK][GBN];
    __shared__ float Cs[GBN][GBM];
    int m0 = blockIdx.x * GBM;
    int n0 = blockIdx.y * GBN;
    int tid = threadIdx.x;
    int tm = tid >> 3, tn = tid & 7;
    float acc[4][4] = {};
    for (int k0 = 0; k0 < K; k0 += GBK) {
        #pragma unroll
        for (int i = 0; i < 4; i++) {
            int q = tid + 256*i;
            int m = q >> 3, f = (q & 7) << 2;
            float4 v = *(const float4*)(A + (size_t)(m0+m)*K + k0 + f);
            As[m][f+0]=v.x; As[m][f+1]=v.y; As[m][f+2]=v.z; As[m][f+3]=v.w;
        }
        #pragma unroll
        for (int i = 0; i < 4; i++) {
            int q = tid + 256*i;
            int kk = q >> 5, n = q & 31;
            float v = 0.f;
            if (n0+n < N) v = Bt[(size_t)(k0+kk)*N + n0+n];
            Bs[kk][n] = v;
        }
        __syncthreads();
        #pragma unroll
        for (int k = 0; k < GBK; k++) {
            float a0 = As[tm*4+0][k], a1 = As[tm*4+1][k];
            float a2 = As[tm*4+2][k], a3 = As[tm*4+3][k];
            float4 bv = *(const float4*)(&Bs[k][tn*4]);
            acc[0][0] = fmaf(a0, bv.x, acc[0][0]); acc[0][1] = fmaf(a0, bv.y, acc[0][1]);
            acc[0][2] = fmaf(a0, bv.z, acc[0][2]); acc[0][3] = fmaf(a0, bv.w, acc[0][3]);
            acc[1][0] = fmaf(a1, bv.x, acc[1][0]); acc[1][1] = fmaf(a1, bv.y, acc[1][1]);
            acc[1][2] = fmaf(a1, bv.z, acc[1][2]); acc[1][3] = fmaf(a1, bv.w, acc[1][3]);
            acc[2][0] = fmaf(a2, bv.x, acc[2][0]); acc[2][1] = fmaf(a2, bv.y, acc[2][1]);
            acc[2][2] = fmaf(a2, bv.z, acc[2][2]); acc[2][3] = fmaf(a2, bv.w, acc[2][3]);
            acc[3][0] = fmaf(a3, bv.x, acc[3][0]); acc[3][1] = fmaf(a3, bv.y, acc[3][1]);
            acc[3][2] = fmaf(a3, bv.z, acc[3][2]); acc[3][3] = fmaf(a3, bv.w, acc[3][3]);
        }
        __syncthreads();
    }
    if (mode == 0) {
        #pragma unroll
        for (int i = 0; i < 4; i++)
            #pragma unroll
            for (int j = 0; j < 4; j++) {
                int n = n0 + tn*4 + j;
                if (n < N) C0[(size_t)(m0 + tm*4 + i)*N + n] = acc[i][j];
            }
    } else if (mode == 1) {
        #pragma unroll
        for (int i = 0; i < 4; i++)
            #pragma unroll
            for (int j = 0; j < 4; j++) {
                int n = n0 + tn*4 + j;
                int m = m0 + tm*4 + i;
                if (n < 192) C0[(size_t)m*192 + n] = acc[i][j];
                else         C1[(size_t)m*192 + (n-192)] = acc[i][j];
            }
    } else {
        #pragma unroll
        for (int i = 0; i < 4; i++)
            #pragma unroll
            for (int j = 0; j < 4; j++)
                Cs[tn*4+j][tm*4+i] = acc[i][j];
        __syncthreads();
        int b = m0 / LL, p0 = m0 % LL;   /* GBM=128 divides LL=2304: no b-crossing */
        for (int e = tid; e < GBN*GBM; e += 256) {
            int n = e >> 7, p = e & 127;
            C0[(size_t)(b*DM + n0 + n)*LL + p0 + p] = Cs[n][p];
        }
    }
}

/* ---------------- depthwise 3x3 conv + bias + SiLU (both paths, one launch) ---------------- */
__global__ void k_conv(const float* __restrict__ cw, const float* __restrict__ cb) {
    int idx = blockIdx.x*blockDim.x + threadIdx.x;
    const int ct = BL*DI;
    if (idx >= 2*ct) return;
    int which = idx >= ct;
    int id = which ? idx - ct : idx;
    const float* in  = which ? g_kvpre : g_qpre;
    float*       out = which ? g_kvc   : g_qc;
    int d = id % DI; int bp = id / DI; int p = bp % LL; int b = bp / LL;
    int h = p / WW, w = p % WW;
    float acc = cb[d];
    #pragma unroll
    for (int i = 0; i < 3; i++) {
        int hh = h + i - 1;
        if (hh < 0 || hh >= HH) continue;
        #pragma unroll
        for (int j = 0; j < 3; j++) {
            int ww = w + j - 1;
            if (ww < 0 || ww >= WW) continue;
            acc = fmaf(in[(b*LL + hh*WW + ww)*DI + d], cw[d*9 + i*3 + j], acc);
        }
    }
    out[id] = acc / (1.f + __expf(-acc));   /* silu */
}

/* ---------------- scatter x_dbl -> dtr / B / C in per-direction scan order ---------------- */
__global__ void k_scatter() {
    int idx = blockIdx.x*blockDim.x + threadIdx.x;
    if (idx >= BL*152) return;
    int bp = idx / 152, t = idx % 152;
    int k = t / 38, c = t % 38;
    int p = bp % LL, b = bp / LL;
    int Tp = (p % WW)*HH + p / WW;
    int lk = (k==0) ? p : (k==1) ? Tp : (k==2) ? (LL-1-p) : (LL-1-Tp);
    float v = g_xdbl[idx];
    int base = (b*KK + k)*LL + lk;
    if (c < 6)       g_dtr[base*RR + c]       = v;
    else if (c < 22) g_Bs [base*NS + (c-6)]   = v;
    else             g_Cs [base*NS + (c-22)]  = v;
}

/* ---------------- selective scan ----------------
   thread = (b,k,d,n); block = 256 = 16 d x 16 n, one (b,k).
   dt computed in staging from rank-6 dtr (kills the 113MB dt stream).
   y written in OUTPUT-position space (gather map is self-consistent). */
__global__ void __launch_bounds__(256) k_scan(const float* __restrict__ A_logs,
                                              const float* __restrict__ Ds,
                                              const float* __restrict__ dtw,
                                              const float* __restrict__ dtb) {
    int bk = blockIdx.y; int b = bk >> 2; int k = bk & 3;
    int d0 = blockIdx.x << 4;
    int tid = threadIdx.x;
    int dd = tid >> 4, n = tid & 15;
    int d = d0 + dd;
    __shared__ float wdt[16][6], bdt[16];
    if (tid < 96) { int c = tid/6, r = tid%6; wdt[c][r] = dtw[(k*DI + d0 + c)*RR + r]; }
    if (tid < 16) bdt[tid] = dtb[k*DI + d0 + tid];
    float A  = -__expf(A_logs[(k*DI + d)*NS + n]);
    float Dv = Ds[k*DI + d];
    float h = 0.f;
    __shared__ float s_dt[CH*16], s_x[CH*16], s_B[CH*16], s_C[CH*16];
    __shared__ int   s_p[CH];
    const int baseL = bk * LL;
    const float* dtrp = g_dtr + baseL*RR;
    const float* Bp   = g_Bs  + baseL*NS;
    const float* Cp   = g_Cs  + baseL*NS;
    const float* xp   = g_qc  + b*LL*DI;
    float*       yp   = g_ydir + baseL*DI;
    __syncthreads();

    for (int l0 = 0; l0 < LL; l0 += CH) {
        #pragma unroll
        for (int i = tid; i < CH*16; i += 256) {
            int r = i >> 4, c = i & 15;
            int l = l0 + r;
            int pos;
            if      (k == 0) pos = l;
            else if (k == 1) pos = (l % WW)*HH + l / WW;
            else if (k == 2) pos = LL-1-l;
            else { int lf = LL-1-l; pos = (lf % WW)*HH + lf / WW; }
            if (c == 0) s_p[r] = pos;
            const float* dr = dtrp + l*RR;
            float a = bdt[c];
            #pragma unroll
            for (int rr = 0; rr < RR; rr++) a = fmaf(dr[rr], wdt[c][rr], a);
            s_dt[i] = (a > 20.f) ? a : __logf(1.f + __expf(a));   /* softplus */
            s_B[i]  = Bp[l*NS + c];
            s_C[i]  = Cp[l*NS + c];
            s_x[i]  = xp[pos*DI + d0 + c];
        }
        __syncthreads();
        #pragma unroll 4
        for (int r = 0; r < CH; r++) {
            float dt = s_dt[(r<<4) + dd];
            float x  = s_x [(r<<4) + dd];
            float Bv = s_B [(r<<4) + n];
            float Cv = s_C [(r<<4) + n];
            float dA = __expf(dt * A);
            h = fmaf(h, dA, dt * x * Bv);
            float y = h * Cv;
            y += __shfl_xor_sync(0xffffffffu, y, 8);
            y += __shfl_xor_sync(0xffffffffu, y, 4);
            y += __shfl_xor_sync(0xffffffffu, y, 2);
            y += __shfl_xor_sync(0xffffffffu, y, 1);
            if (n == 0) yp[s_p[r]*DI + d] = fmaf(Dv, x, y);
        }
        __syncthreads();
    }
}

/* ---------------- direction merge + LayerNorm + z ---------------- */
__global__ void k_lnz(const float* __restrict__ lnw, const float* __restrict__ lnb) {
    int bp = blockIdx.x; int p = bp % LL; int b = bp / LL;
    int tid = threadIdx.x;              /* 192 */
    int b4 = b * KK;
    float v = g_ydir[((b4+0)*LL + p)*DI + tid]
            + g_ydir[((b4+1)*LL + p)*DI + tid]
            + g_ydir[((b4+2)*LL + p)*DI + tid]
            + g_ydir[((b4+3)*LL + p)*DI + tid];
    __shared__ float red[6];
    float s = v;
    #pragma unroll
    for (int o = 16; o; o >>= 1) s += __shfl_xor_sync(0xffffffffu, s, o);
    if ((tid & 31) == 0) red[tid >> 5] = s;
    __syncthreads();
    float mu = (red[0]+red[1]+red[2]+red[3]+red[4]+red[5]) * (1.f/DI);
    __syncthreads();
    float dv = v - mu;
    float s2 = dv*dv;
    #pragma unroll
    for (int o = 16; o; o >>= 1) s2 += __shfl_xor_sync(0xffffffffu, s2, o);
    if ((tid & 31) == 0) red[tid >> 5] = s2;
    __syncthreads();
    float var = (red[0]+red[1]+red[2]+red[3]+red[4]+red[5]) * (1.f/DI);
    float rstd = rsqrtf(var + 1e-5f);
    g_yln[bp*DI + tid] = fmaf(dv*rstd, lnw[tid], lnb[tid]) + g_z[bp*DI + tid];
}

/* ---------------- launch ---------------- */
extern "C" void kernel_launch(void* const* d_in, const int* in_sizes, int n_in,
                              void* d_out, int out_size) {
    const float* q_x    = (const float*)d_in[0];
    const float* kv_x   = (const float*)d_in[1];
    const float* w1     = (const float*)d_in[2];
    const float* w2     = (const float*)d_in[3];
    const float* cw     = (const float*)d_in[4];
    const float* cb     = (const float*)d_in[5];
    const float* xpw    = (const float*)d_in[6];
    const float* dtw    = (const float*)d_in[7];
    const float* dtb    = (const float*)d_in[8];
    const float* A_logs = (const float*)d_in[9];
    const float* Ds     = (const float*)d_in[10];
    const float* lnw    = (const float*)d_in[11];
    const float* lnb    = (const float*)d_in[12];
    const float* wout   = (const float*)d_in[13];
    float* out = (float*)d_out;

    float *p_qpre, *p_kvpre, *p_kvc, *p_z, *p_xdbl, *p_yln;
    float *p_w1T, *p_w2T, *p_xpwT, *p_woutT;
    cudaGetSymbolAddress((void**)&p_qpre,  g_qpre);
    cudaGetSymbolAddress((void**)&p_kvpre, g_kvpre);
    cudaGetSymbolAddress((void**)&p_kvc,   g_kvc);
    cudaGetSymbolAddress((void**)&p_z,     g_z);
    cudaGetSymbolAddress((void**)&p_xdbl,  g_xdbl);
    cudaGetSymbolAddress((void**)&p_yln,   g_yln);
    cudaGetSymbolAddress((void**)&p_w1T,   g_w1T);
    cudaGetSymbolAddress((void**)&p_w2T,   g_w2T);
    cudaGetSymbolAddress((void**)&p_xpwT,  g_xpwT);
    cudaGetSymbolAddress((void**)&p_woutT, g_woutT);

    const int prepN = 384*96 + 192*96 + KK*38*192 + 96*192;
    k_prep<<<(prepN + 255)/256, 256>>>(w1, w2, xpw, wout);

    /* in_proj q (split q/z) and kv */
    k_gemm<<<dim3(BL/GBM, 384/GBN), 256>>>(q_x,  p_w1T, p_qpre, p_z, 96, 384, 1);
    k_gemm<<<dim3(BL/GBM, 192/GBN), 256>>>(kv_x, p_w2T, p_kvpre, nullptr, 96, 192, 0);

    k_conv<<<(2*BL*DI + 255)/256, 256>>>(cw, cb);

    /* x_proj: [BL,192] x [192,152] */
    k_gemm<<<dim3(BL/GBM, (152+GBN-1)/GBN), 256>>>(p_kvc, p_xpwT, p_xdbl, nullptr, 192, 152, 0);
    k_scatter<<<(BL*152 + 255)/256, 256>>>();

    dim3 sg(DI/16, BB*KK);
    k_scan<<<sg, 256>>>(A_logs, Ds, dtw, dtb);

    k_lnz<<<BL, 192>>>(lnw, lnb);

    /* out_proj with transposed store: [BL,192] x [192,96] -> (B,DM,H,W) */
    k_gemm<<<dim3(BL/GBM, 96/GBN), 256>>>(p_yln, p_woutT, out, nullptr, 192, 96, 2);
}

// round 4
// speedup vs baseline: 1.4573x; 1.0509x over previous
#include <cuda_runtime.h>

#define BB 8
#define HH 48
#define WW 48
#define LL (HH*WW)      /* 2304 */
#define DM 96
#define DI 192
#define NS 16
#define RR 6
#define KK 4
#define CH 32           /* scan steps staged per chunk */
#define BL (BB*LL)      /* 18432 */
#define SDN 32          /* d-channels per scan block */

#define GBM 128
#define GBN 32
#define GBK 32

/* ---------------- scratch (static device globals; no allocation) ---------------- */
__device__ float g_qpre [BL*DI];
__device__ float g_kvpre[BL*DI];
__device__ float g_qc   [BL*DI];
__device__ float g_kvc  [BL*DI];
__device__ float g_z    [BL*DI];
__device__ float g_dtr  [BB*KK*LL*RR];
__device__ float g_Bs   [BB*KK*LL*NS];
__device__ float g_Cs   [BB*KK*LL*NS];
__device__ float g_ydir [BB*KK*LL*DI];   /* position-space per direction */
__device__ float g_yln  [BL*DI];
__device__ float g_w1T  [DM*2*DI];       /* [m][o] 96x384 */
__device__ float g_w2T  [DM*DI];         /* [m][o] 96x192 */
__device__ float g_xpwT [DI*152];        /* [d][k*38+c]   */
__device__ float g_woutT[DI*DM];         /* [e][m] 192x96 */
__device__ float g_cwT  [9*DI];          /* [tap][d]      */

/* ---------------- weight transposes ---------------- */
__global__ void k_prep(const float* __restrict__ w1, const float* __restrict__ w2,
                       const float* __restrict__ xpw, const float* __restrict__ wout,
                       const float* __restrict__ cw) {
    const int O1 = 384*96;
    const int O2 = O1 + 192*96;
    const int O3 = O2 + KK*38*192;
    const int O4 = O3 + 96*192;
    const int O5 = O4 + 9*DI;
    int i = blockIdx.x*blockDim.x + threadIdx.x;
    if (i < O1) {
        int o = i / 96, m = i % 96;
        g_w1T[m*384 + o] = w1[i];
    } else if (i < O2) {
        int j = i - O1; int o = j/96, m = j%96;
        g_w2T[m*192 + o] = w2[j];
    } else if (i < O3) {
        int a = i - O2; int k = a/7296; int rem = a%7296; int c = rem/192, d = rem%192;
        g_xpwT[d*152 + k*38 + c] = xpw[a];
    } else if (i < O4) {
        int f = i - O3; int m = f/192, d = f%192;
        g_woutT[d*DM + m] = wout[f];
    } else if (i < O5) {
        int e = i - O4; int d = e/9, t = e%9;
        g_cwT[t*DI + d] = cw[e];
    }
}

/* ---------------- register-tiled GEMM:  C[M,N] = A[M,K] * Bt[K,N] ----------------
   mode 0: plain store to C0[M,N]
   mode 1: split cols: col<192 -> C0[m*192+col], else C1[m*192+col-192]
   mode 2: transposed store: C0[(b*96 + col)*LL + p], m = b*LL + p
   mode 3: xproj fused scatter into g_dtr / g_Bs / g_Cs (per-direction scan order) */
__global__ void __launch_bounds__(256) k_gemm(const float* __restrict__ A,
                                              const float* __restrict__ Bt,
                                              float* __restrict__ C0,
                                              float* __restrict__ C1,
                                              int K, int N, int mode) {
    __shared__ float As[GBM][36];
    __shared__ float Bs[GBK][GBN];
    __shared__ float Cs[GBN][GBM];
    int m0 = blockIdx.x * GBM;
    int n0 = blockIdx.y * GBN;
    int tid = threadIdx.x;
    int tm = tid >> 3, tn = tid & 7;
    float acc[4][4] = {};
    for (int k0 = 0; k0 < K; k0 += GBK) {
        #pragma unroll
        for (int i = 0; i < 4; i++) {
            int q = tid + 256*i;
            int m = q >> 3, f = (q & 7) << 2;
            float4 v = *(const float4*)(A + (size_t)(m0+m)*K + k0 + f);
            As[m][f+0]=v.x; As[m][f+1]=v.y; As[m][f+2]=v.z; As[m][f+3]=v.w;
        }
        #pragma unroll
        for (int i = 0; i < 4; i++) {
            int q = tid + 256*i;
            int kk = q >> 5, n = q & 31;
            float v = 0.f;
            if (n0+n < N) v = Bt[(size_t)(k0+kk)*N + n0+n];
            Bs[kk][n] = v;
        }
        __syncthreads();
        #pragma unroll
        for (int k = 0; k < GBK; k++) {
            float a0 = As[tm*4+0][k], a1 = As[tm*4+1][k];
            float a2 = As[tm*4+2][k], a3 = As[tm*4+3][k];
            float4 bv = *(const float4*)(&Bs[k][tn*4]);
            acc[0][0] = fmaf(a0, bv.x, acc[0][0]); acc[0][1] = fmaf(a0, bv.y, acc[0][1]);
            acc[0][2] = fmaf(a0, bv.z, acc[0][2]); acc[0][3] = fmaf(a0, bv.w, acc[0][3]);
            acc[1][0] = fmaf(a1, bv.x, acc[1][0]); acc[1][1] = fmaf(a1, bv.y, acc[1][1]);
            acc[1][2] = fmaf(a1, bv.z, acc[1][2]); acc[1][3] = fmaf(a1, bv.w, acc[1][3]);
            acc[2][0] = fmaf(a2, bv.x, acc[2][0]); acc[2][1] = fmaf(a2, bv.y, acc[2][1]);
            acc[2][2] = fmaf(a2, bv.z, acc[2][2]); acc[2][3] = fmaf(a2, bv.w, acc[2][3]);
            acc[3][0] = fmaf(a3, bv.x, acc[3][0]); acc[3][1] = fmaf(a3, bv.y, acc[3][1]);
            acc[3][2] = fmaf(a3, bv.z, acc[3][2]); acc[3][3] = fmaf(a3, bv.w, acc[3][3]);
        }
        __syncthreads();
    }
    if (mode == 0) {
        #pragma unroll
        for (int i = 0; i < 4; i++)
            #pragma unroll
            for (int j = 0; j < 4; j++) {
                int n = n0 + tn*4 + j;
                if (n < N) C0[(size_t)(m0 + tm*4 + i)*N + n] = acc[i][j];
            }
    } else if (mode == 1) {
        #pragma unroll
        for (int i = 0; i < 4; i++)
            #pragma unroll
            for (int j = 0; j < 4; j++) {
                int n = n0 + tn*4 + j;
                int m = m0 + tm*4 + i;
                if (n < 192) C0[(size_t)m*192 + n] = acc[i][j];
                else         C1[(size_t)m*192 + (n-192)] = acc[i][j];
            }
    } else if (mode == 2) {
        #pragma unroll
        for (int i = 0; i < 4; i++)
            #pragma unroll
            for (int j = 0; j < 4; j++)
                Cs[tn*4+j][tm*4+i] = acc[i][j];
        __syncthreads();
        int b = m0 / LL, p0 = m0 % LL;   /* GBM=128 divides LL=2304: no b-crossing */
        for (int e = tid; e < GBN*GBM; e += 256) {
            int n = e >> 7, p = e & 127;
            C0[(size_t)(b*DM + n0 + n)*LL + p0 + p] = Cs[n][p];
        }
    } else {
        /* xproj scatter: t = column in [0,152) -> (k, c); write dtr/B/C in scan order */
        #pragma unroll
        for (int i = 0; i < 4; i++) {
            int m = m0 + tm*4 + i;
            int bb = m / LL, p = m % LL;
            int Tp = (p % WW)*HH + p / WW;
            int fp = LL-1-p, fTp = LL-1-Tp;
            #pragma unroll
            for (int j = 0; j < 4; j++) {
                int t = n0 + tn*4 + j;
                if (t >= 152) continue;
                int kq = t / 38, c = t % 38;
                int lk = (kq==0) ? p : (kq==1) ? Tp : (kq==2) ? fp : fTp;
                int base = (bb*KK + kq)*LL + lk;
                float v = acc[i][j];
                if (c < 6)       g_dtr[base*RR + c]      = v;
                else if (c < 22) g_Bs [base*NS + (c-6)]  = v;
                else             g_Cs [base*NS + (c-22)] = v;
            }
        }
    }
}

/* ---------------- depthwise 3x3 conv + bias + SiLU, float4 over d ---------------- */
__global__ void k_conv(const float* __restrict__ cb) {
    int idx = blockIdx.x*blockDim.x + threadIdx.x;
    const int ct = BL*(DI/4);
    if (idx >= 2*ct) return;
    int which = idx >= ct;
    int id = which ? idx - ct : idx;
    const float* in  = which ? g_kvpre : g_qpre;
    float*       out = which ? g_kvc   : g_qc;
    int d4 = id % (DI/4); int bp = id / (DI/4); int p = bp % LL; int b = bp / LL;
    int h = p / WW, w = p % WW;
    int dof = d4 * 4;
    float4 acc = *(const float4*)(cb + dof);
    #pragma unroll
    for (int i = 0; i < 3; i++) {
        int hh = h + i - 1;
        if (hh < 0 || hh >= HH) continue;
        #pragma unroll
        for (int j = 0; j < 3; j++) {
            int ww = w + j - 1;
            if (ww < 0 || ww >= WW) continue;
            float4 v = *(const float4*)(in + (size_t)(b*LL + hh*WW + ww)*DI + dof);
            float4 wt = *(const float4*)(g_cwT + (i*3+j)*DI + dof);
            acc.x = fmaf(v.x, wt.x, acc.x);
            acc.y = fmaf(v.y, wt.y, acc.y);
            acc.z = fmaf(v.z, wt.z, acc.z);
            acc.w = fmaf(v.w, wt.w, acc.w);
        }
    }
    acc.x = acc.x / (1.f + __expf(-acc.x));
    acc.y = acc.y / (1.f + __expf(-acc.y));
    acc.z = acc.z / (1.f + __expf(-acc.z));
    acc.w = acc.w / (1.f + __expf(-acc.w));
    *(float4*)(out + (size_t)bp*DI + dof) = acc;
}

/* ---------------- selective scan ----------------
   warp = 8 d x 4 lanes; each lane holds 4 h-states (n = 4g..4g+3) in registers.
   Per warp-step: ~5 LDS + 2 SHFL (MIO-lean), 4 MUFU, ~22 FMA.
   dt recomputed from rank-6 dtr in staging. y written in output-position space. */
__global__ void __launch_bounds__(128) k_scan(const float* __restrict__ A_logs,
                                              const float* __restrict__ Ds,
                                              const float* __restrict__ dtw,
                                              const float* __restrict__ dtb) {
    int bk = blockIdx.y; int b = bk >> 2; int k = bk & 3;
    int d0 = blockIdx.x * SDN;
    int tid = threadIdx.x;              /* 128 */
    int dl = tid >> 2;                  /* 0..31 local d */
    int g  = tid & 3;                   /* n-group */
    int d = d0 + dl;

    float A0 = -__expf(A_logs[(k*DI + d)*NS + 4*g + 0]);
    float A1 = -__expf(A_logs[(k*DI + d)*NS + 4*g + 1]);
    float A2 = -__expf(A_logs[(k*DI + d)*NS + 4*g + 2]);
    float A3 = -__expf(A_logs[(k*DI + d)*NS + 4*g + 3]);
    float Dv = Ds[k*DI + d];
    float h0 = 0.f, h1 = 0.f, h2 = 0.f, h3 = 0.f;

    __shared__ float wdt[SDN][8], bdt[SDN];
    if (tid < SDN) bdt[tid] = dtb[k*DI + d0 + tid];
    for (int i = tid; i < SDN*RR; i += 128)
        wdt[i/RR][i%RR] = dtw[(k*DI + d0 + i/RR)*RR + (i%RR)];

    __shared__ __align__(16) float s_dt[CH*SDN], s_x[CH*SDN];
    __shared__ __align__(16) float s_B[CH*NS], s_C[CH*NS];
    __shared__ float s_dtr[CH*8];
    __shared__ int   s_p[CH];

    const int baseL = bk * LL;
    const float* dtrp = g_dtr + (size_t)baseL*RR;
    const float* Bp   = g_Bs  + (size_t)baseL*NS;
    const float* Cp   = g_Cs  + (size_t)baseL*NS;
    const float* xp   = g_qc  + (size_t)b*LL*DI;
    float*       yp   = g_ydir + (size_t)baseL*DI;
    __syncthreads();

    for (int l0 = 0; l0 < LL; l0 += CH) {
        /* phase 1: dtr, B, C, positions */
        #pragma unroll
        for (int i = tid; i < CH*RR; i += 128)
            s_dtr[(i/RR)*8 + (i%RR)] = dtrp[(size_t)(l0 + i/RR)*RR + (i%RR)];
        #pragma unroll
        for (int i = tid; i < CH*NS; i += 128) {
            int r = i >> 4, c = i & 15;
            s_B[i] = Bp[(size_t)(l0+r)*NS + c];
            s_C[i] = Cp[(size_t)(l0+r)*NS + c];
        }
        if (tid < CH) {
            int l = l0 + tid;
            int pos;
            if      (k == 0) pos = l;
            else if (k == 1) pos = (l % WW)*HH + l / WW;
            else if (k == 2) pos = LL-1-l;
            else { int lf = LL-1-l; pos = (lf % WW)*HH + lf / WW; }
            s_p[tid] = pos;
        }
        __syncthreads();
        /* phase 2: dt (softplus of rank-6 proj) + x gather */
        #pragma unroll
        for (int i = tid; i < CH*SDN; i += 128) {
            int r = i >> 5, c = i & 31;
            float a = bdt[c];
            #pragma unroll
            for (int rr = 0; rr < RR; rr++)
                a = fmaf(s_dtr[r*8 + rr], wdt[c][rr], a);
            s_dt[i] = (a > 20.f) ? a : __logf(1.f + __expf(a));
            s_x[i]  = xp[(size_t)s_p[r]*DI + d0 + c];
        }
        __syncthreads();
        /* phase 3: recurrence */
        #pragma unroll 4
        for (int r = 0; r < CH; r++) {
            float dt = s_dt[(r<<5) + dl];
            float x  = s_x [(r<<5) + dl];
            float4 Bv = *(const float4*)(&s_B[(r<<4) + g*4]);
            float4 Cv = *(const float4*)(&s_C[(r<<4) + g*4]);
            float u = dt * x;
            float dA0 = __expf(dt * A0);
            float dA1 = __expf(dt * A1);
            float dA2 = __expf(dt * A2);
            float dA3 = __expf(dt * A3);
            h0 = fmaf(h0, dA0, u * Bv.x);
            h1 = fmaf(h1, dA1, u * Bv.y);
            h2 = fmaf(h2, dA2, u * Bv.z);
            h3 = fmaf(h3, dA3, u * Bv.w);
            float y = h0 * Cv.x;
            y = fmaf(h1, Cv.y, y);
            y = fmaf(h2, Cv.z, y);
            y = fmaf(h3, Cv.w, y);
            y += __shfl_xor_sync(0xffffffffu, y, 1);
            y += __shfl_xor_sync(0xffffffffu, y, 2);
            if (g == 0) yp[(size_t)s_p[r]*DI + d] = fmaf(Dv, x, y);
        }
        __syncthreads();
    }
}

/* ---------------- direction merge + LayerNorm + z ---------------- */
__global__ void k_lnz(const float* __restrict__ lnw, const float* __restrict__ lnb) {
    int bp = blockIdx.x; int p = bp % LL; int b = bp / LL;
    int tid = threadIdx.x;              /* 192 */
    int b4 = b * KK;
    float v = g_ydir[(size_t)((b4+0)*LL + p)*DI + tid]
            + g_ydir[(size_t)((b4+1)*LL + p)*DI + tid]
            + g_ydir[(size_t)((b4+2)*LL + p)*DI + tid]
            + g_ydir[(size_t)((b4+3)*LL + p)*DI + tid];
    __shared__ float red[6];
    float s = v;
    #pragma unroll
    for (int o = 16; o; o >>= 1) s += __shfl_xor_sync(0xffffffffu, s, o);
    if ((tid & 31) == 0) red[tid >> 5] = s;
    __syncthreads();
    float mu = (red[0]+red[1]+red[2]+red[3]+red[4]+red[5]) * (1.f/DI);
    __syncthreads();
    float dv = v - mu;
    float s2 = dv*dv;
    #pragma unroll
    for (int o = 16; o; o >>= 1) s2 += __shfl_xor_sync(0xffffffffu, s2, o);
    if ((tid & 31) == 0) red[tid >> 5] = s2;
    __syncthreads();
    float var = (red[0]+red[1]+red[2]+red[3]+red[4]+red[5]) * (1.f/DI);
    float rstd = rsqrtf(var + 1e-5f);
    g_yln[(size_t)bp*DI + tid] = fmaf(dv*rstd, lnw[tid], lnb[tid]) + g_z[(size_t)bp*DI + tid];
}

/* ---------------- launch ---------------- */
extern "C" void kernel_launch(void* const* d_in, const int* in_sizes, int n_in,
                              void* d_out, int out_size) {
    const float* q_x    = (const float*)d_in[0];
    const float* kv_x   = (const float*)d_in[1];
    const float* w1     = (const float*)d_in[2];
    const float* w2     = (const float*)d_in[3];
    const float* cw     = (const float*)d_in[4];
    const float* cb     = (const float*)d_in[5];
    const float* xpw    = (const float*)d_in[6];
    const float* dtw    = (const float*)d_in[7];
    const float* dtb    = (const float*)d_in[8];
    const float* A_logs = (const float*)d_in[9];
    const float* Ds     = (const float*)d_in[10];
    const float* lnw    = (const float*)d_in[11];
    const float* lnb    = (const float*)d_in[12];
    const float* wout   = (const float*)d_in[13];
    float* out = (float*)d_out;

    float *p_qpre, *p_kvpre, *p_kvc, *p_z, *p_yln;
    float *p_w1T, *p_w2T, *p_xpwT, *p_woutT;
    cudaGetSymbolAddress((void**)&p_qpre,  g_qpre);
    cudaGetSymbolAddress((void**)&p_kvpre, g_kvpre);
    cudaGetSymbolAddress((void**)&p_kvc,   g_kvc);
    cudaGetSymbolAddress((void**)&p_z,     g_z);
    cudaGetSymbolAddress((void**)&p_yln,   g_yln);
    cudaGetSymbolAddress((void**)&p_w1T,   g_w1T);
    cudaGetSymbolAddress((void**)&p_w2T,   g_w2T);
    cudaGetSymbolAddress((void**)&p_xpwT,  g_xpwT);
    cudaGetSymbolAddress((void**)&p_woutT, g_woutT);

    const int prepN = 384*96 + 192*96 + KK*38*192 + 96*192 + 9*DI;
    k_prep<<<(prepN + 255)/256, 256>>>(w1, w2, xpw, wout, cw);

    /* in_proj q (split q/z) and kv */
    k_gemm<<<dim3(BL/GBM, 384/GBN), 256>>>(q_x,  p_w1T, p_qpre, p_z, 96, 384, 1);
    k_gemm<<<dim3(BL/GBM, 192/GBN), 256>>>(kv_x, p_w2T, p_kvpre, nullptr, 96, 192, 0);

    k_conv<<<(2*BL*(DI/4) + 255)/256, 256>>>(cb);

    /* x_proj with fused per-direction scatter: [BL,192] x [192,152] */
    k_gemm<<<dim3(BL/GBM, (152+GBN-1)/GBN), 256>>>(p_kvc, p_xpwT, nullptr, nullptr, 192, 152, 3);

    dim3 sg(DI/SDN, BB*KK);
    k_scan<<<sg, 128>>>(A_logs, Ds, dtw, dtb);

    k_lnz<<<BL, 192>>>(lnw, lnb);

    /* out_proj with transposed store: [BL,192] x [192,96] -> (B,DM,H,W) */
    k_gemm<<<dim3(BL/GBM, 96/GBN), 256>>>(p_yln, p_woutT, out, nullptr, 192, 96, 2);
}